// round 12
// baseline (speedup 1.0000x reference)
#include <cuda_runtime.h>
#include <cuda_bf16.h>
#include <math.h>
#include <stdint.h>

constexpr int Bv = 16, Nv = 2000, Wv = 32, Fv = 5;
constexpr int TH = 128, SH = 64, HEADS = 4;
constexpr int Mn = Bv * Nv, EB = 32000, ET = Bv * EB + Mn;

// ---------------- device scratch ----------------
__device__ float g_h1[(size_t)Mn * TH];
__device__ float g_xp[(size_t)Mn * SH];
__device__ float g_asrc[Mn * HEADS];
__device__ float g_adst[Mn * HEADS];
__device__ float g_den[Mn * HEADS];
__device__ float g_agg[(size_t)Mn * SH];
__device__ int   g_ei_is64;
// B packs: uint4 = (bh_r0, bh_r1, bl_r0, bl_r1) per (ch, gate, jslot, lane)
constexpr int Q1N = 16 * 4 * 16 * 32;   // 32768
constexpr int Q0N = 8 * 3 * 16 * 32;    // 12288
__device__ uint4 g_Q1[Q1N];
__device__ uint4 g_Q0[Q0N];

__device__ __forceinline__ float sigf(float x) {
    return __fdividef(1.f, 1.f + __expf(-x));
}
__device__ __forceinline__ float tanhfast(float x) {
    float e = __expf(2.f * x);
    return 1.f - __fdividef(2.f, e + 1.f);
}

__device__ __forceinline__ void mma16816(float* c, const uint32_t* a,
                                         uint32_t b0, uint32_t b1) {
    asm volatile(
        "mma.sync.aligned.m16n8k16.row.col.f32.bf16.bf16.f32 "
        "{%0,%1,%2,%3}, {%4,%5,%6,%7}, {%8,%9}, {%0,%1,%2,%3};\n"
        : "+f"(c[0]), "+f"(c[1]), "+f"(c[2]), "+f"(c[3])
        : "r"(a[0]), "r"(a[1]), "r"(a[2]), "r"(a[3]), "r"(b0), "r"(b1));
}

__device__ __forceinline__ uint32_t pack_bf16x2(float f0, float f1, uint32_t& lo_out) {
    __nv_bfloat16 h0 = __float2bfloat16(f0);
    __nv_bfloat16 h1 = __float2bfloat16(f1);
    __nv_bfloat16 l0 = __float2bfloat16(f0 - __bfloat162float(h0));
    __nv_bfloat16 l1 = __float2bfloat16(f1 - __bfloat162float(h1));
    lo_out = (uint32_t)__bfloat16_as_ushort(l0) | ((uint32_t)__bfloat16_as_ushort(l1) << 16);
    return (uint32_t)__bfloat16_as_ushort(h0) | ((uint32_t)__bfloat16_as_ushort(h1) << 16);
}
__device__ __forceinline__ float bf_lo(uint32_t w) {
    return __bfloat162float(__ushort_as_bfloat16((unsigned short)(w & 0xffff)));
}
__device__ __forceinline__ float bf_hi(uint32_t w) {
    return __bfloat162float(__ushort_as_bfloat16((unsigned short)(w >> 16)));
}

// ---------------- edge-index dtype probe ----------------
__global__ void detect_ei_kernel(const int* __restrict__ w) {
    __shared__ int nz;
    if (threadIdx.x == 0) nz = 0;
    __syncthreads();
    for (int i = threadIdx.x; i < 2048; i += blockDim.x)
        if ((i & 1) && w[i] != 0) atomicOr(&nz, 1);
    __syncthreads();
    if (threadIdx.x == 0) g_ei_is64 = nz ? 0 : 1;
}

// ---------------- prep: pack weights into uint4 MMA fragments ----------------
__global__ void prep_pack(const float* __restrict__ Wih1,
                          const float* __restrict__ Whh1,
                          const float* __restrict__ Whh0) {
    int idx = blockIdx.x * blockDim.x + threadIdx.x;
    if (idx < Q1N) {
        int lane = idx & 31, js = (idx >> 5) & 15, g = (idx >> 9) & 3, ch = idx >> 11;
        int j = js * 8 + (lane >> 2);
        float v[2][2];
#pragma unroll
        for (int r = 0; r < 2; ++r) {
            int k0 = ch * 16 + (lane & 3) * 2 + r * 8;
            float a = 0.f, b = 0.f;
            if (ch < 8) {
                if (g < 3) {
                    const float* Wr = Wih1 + (size_t)(g * 128 + j) * 128;
                    a = Wr[k0]; b = Wr[k0 + 1];
                }
            } else {
                int km = k0 - 128;
                if (g != 2) {
                    int gg = (g == 3) ? 2 : g;
                    const float* Wr = Whh1 + (size_t)(gg * 128 + j) * 128;
                    a = Wr[km]; b = Wr[km + 1];
                }
            }
            v[r][0] = a; v[r][1] = b;
        }
        uint4 o;
        uint32_t lo0, lo1;
        o.x = pack_bf16x2(v[0][0], v[0][1], lo0);
        o.y = pack_bf16x2(v[1][0], v[1][1], lo1);
        o.z = lo0; o.w = lo1;
        g_Q1[idx] = o;
    } else if (idx < Q1N + Q0N) {
        int i0 = idx - Q1N;
        int lane = i0 & 31, js = (i0 >> 5) & 15;
        int rest = i0 >> 9;
        int g = rest % 3, ch = rest / 3;
        int j = js * 8 + (lane >> 2);
        const float* Wr = Whh0 + (size_t)(g * 128 + j) * 128;
        uint4 o;
        uint32_t lo0, lo1;
        int k0 = ch * 16 + (lane & 3) * 2;
        o.x = pack_bf16x2(Wr[k0], Wr[k0 + 1], lo0);
        o.y = pack_bf16x2(Wr[k0 + 8], Wr[k0 + 9], lo1);
        o.z = lo0; o.w = lo1;
        g_Q0[i0] = o;
    }
}

__global__ void zero_kernel() {
    size_t stride = (size_t)gridDim.x * blockDim.x;
    for (size_t i = (size_t)blockIdx.x * blockDim.x + threadIdx.x;
         i < (size_t)Mn * SH; i += stride) {
        g_agg[i] = 0.f;
        if (i < (size_t)Mn * HEADS) g_den[i] = 0.f;
    }
}

#define MMA3(accp, ahv, alv, bq)              \
    mma16816(accp, ahv, (bq).x, (bq).y);      \
    mma16816(accp, alv, (bq).x, (bq).y);      \
    mma16816(accp, ahv, (bq).z, (bq).w);

// ===== persistent GRU: grid 2000 (M=16 tiles), block 128 (4 warps), 5 CTAs/SM =====
// smem: state hi[16*512] | lo[16*512] | sW[1920 f] | sb[1024 f] | sX[80 f]
constexpr int SM_SLO = 8192;
constexpr int SM_SW  = 16384;
constexpr int SM_SB  = SM_SW + 7680;    // 24064
constexpr int SM_SX  = SM_SB + 4096;    // 28160
constexpr int SM_TOT = SM_SX + 320;     // 28480

__global__ __launch_bounds__(128, 5)
void gru_all(const float* __restrict__ X, const float* __restrict__ Wih0,
             const float* __restrict__ bi0, const float* __restrict__ bh0,
             const float* __restrict__ bi1, const float* __restrict__ bh1) {
    extern __shared__ char sm[];
    char* shi = sm;
    char* slo = sm + SM_SLO;
    float* sW = (float*)(sm + SM_SW);
    float* sb = (float*)(sm + SM_SB);
    float* sX = (float*)(sm + SM_SX);

    const int tid = threadIdx.x, lane = tid & 31, wn = tid >> 5;
    const int m0 = blockIdx.x * 16;
    const int fragbase = lane * 16;

    {
        uint4 z = make_uint4(0, 0, 0, 0);
        for (int i = tid; i < 512; i += 128) {
            ((uint4*)shi)[i] = z;
            ((uint4*)slo)[i] = z;
        }
    }
    for (int i = tid; i < 384 * Fv; i += 128) sW[i] = Wih0[i];
    for (int i = tid; i < 1024; i += 128) {
        int j = i & 127, which = (i >> 7) & 3, L = i >> 9;
        const float* BI = L ? bi1 : bi0;
        const float* BH = L ? bh1 : bh0;
        float v;
        if (which == 0)      v = BI[j] + BH[j];
        else if (which == 1) v = BI[128 + j] + BH[128 + j];
        else if (which == 2) v = BI[256 + j];
        else                 v = BH[256 + j];
        sb[i] = v;
    }
    __syncthreads();

    for (int t = 0; t < Wv; ++t) {
        uint4 hqh[2], hql[2];   // [pass]

        // X prefetch (each warp writes all 80; identical values, benign)
        for (int i = lane; i < 80; i += 32) {
            int rr = i / 5, f = i - rr * 5;
            sX[i] = X[((size_t)(m0 + rr) * Wv + t) * Fv + f];
        }
        __syncwarp();

        // ================= LAYER 0 =================
        for (int p = 0; p < 2; ++p) {
            float acc[3][2][4];
#pragma unroll
            for (int g = 0; g < 3; ++g)
#pragma unroll
                for (int nt = 0; nt < 2; ++nt)
#pragma unroll
                    for (int e = 0; e < 4; ++e) acc[g][nt][e] = 0.f;
            const int js0 = p * 8 + wn * 2;
#pragma unroll 2
            for (int ch = 0; ch < 8; ++ch) {
                const int cb = ch * 512 + fragbase;
                uint32_t ah[4], al[4];
                {
                    uint4 vh = *(const uint4*)(shi + cb);
                    uint4 vl = *(const uint4*)(slo + cb);
                    ah[0] = vh.x; ah[1] = vh.y; ah[2] = vh.z; ah[3] = vh.w;
                    al[0] = vl.x; al[1] = vl.y; al[2] = vl.z; al[3] = vl.w;
                }
#pragma unroll
                for (int g = 0; g < 3; ++g)
#pragma unroll
                    for (int nt = 0; nt < 2; ++nt) {
                        uint4 b = g_Q0[((ch * 3 + g) * 16 + js0 + nt) * 32 + lane];
                        MMA3(acc[g][nt], ah, al, b);
                    }
            }
            // epilogue L0 (pass p)
            {
                const int hpaddr = (p * 4 + wn) * 512 + fragbase;
                uint4 ph = *(const uint4*)(shi + hpaddr);
                uint4 pl = *(const uint4*)(slo + hpaddr);
                uint32_t phA[4] = {ph.x, ph.y, ph.z, ph.w};
                uint32_t plA[4] = {pl.x, pl.y, pl.z, pl.w};
                uint32_t vhi[4], vlo[4];
#pragma unroll
                for (int half = 0; half < 2; ++half) {
                    const int r = (lane >> 2) + half * 8;
                    float xv[Fv];
#pragma unroll
                    for (int f = 0; f < Fv; ++f) xv[f] = sX[r * 5 + f];
#pragma unroll
                    for (int nt = 0; nt < 2; ++nt) {
                        const int fi = nt * 2 + half;
                        const int jb = p * 64 + wn * 16 + nt * 8 + (lane & 3) * 2;
                        float hp[2] = { bf_lo(phA[fi]) + bf_lo(plA[fi]),
                                        bf_hi(phA[fi]) + bf_hi(plA[fi]) };
                        float h2[2];
#pragma unroll
                        for (int e = 0; e < 2; ++e) {
                            int j = jb + e;
                            float sR = 0.f, sZ = 0.f, sI = 0.f;
#pragma unroll
                            for (int f = 0; f < Fv; ++f) {
                                sR = fmaf(xv[f], sW[j * Fv + f], sR);
                                sZ = fmaf(xv[f], sW[(128 + j) * Fv + f], sZ);
                                sI = fmaf(xv[f], sW[(256 + j) * Fv + f], sI);
                            }
                            int c = half * 2 + e;
                            float rr = sigf(acc[0][nt][c] + sR + sb[j]);
                            float zz = sigf(acc[1][nt][c] + sZ + sb[128 + j]);
                            float nn = tanhfast(sI + sb[256 + j] +
                                                rr * (acc[2][nt][c] + sb[384 + j]));
                            h2[e] = (1.f - zz) * nn + zz * hp[e];
                        }
                        vhi[fi] = pack_bf16x2(h2[0], h2[1], vlo[fi]);
                    }
                }
                hqh[p] = make_uint4(vhi[0], vhi[1], vhi[2], vhi[3]);
                hql[p] = make_uint4(vlo[0], vlo[1], vlo[2], vlo[3]);
            }
        }
        __syncthreads();
#pragma unroll
        for (int p = 0; p < 2; ++p) {
            const int a = (p * 4 + wn) * 512 + fragbase;
            *(uint4*)(shi + a) = hqh[p];
            *(uint4*)(slo + a) = hql[p];
        }
        __syncthreads();

        // ================= LAYER 1 =================
        for (int p = 0; p < 2; ++p) {
            float acc[4][2][4];
#pragma unroll
            for (int g = 0; g < 4; ++g)
#pragma unroll
                for (int nt = 0; nt < 2; ++nt)
#pragma unroll
                    for (int e = 0; e < 4; ++e) acc[g][nt][e] = 0.f;
            const int js0 = p * 8 + wn * 2;
#pragma unroll 2
            for (int ch = 0; ch < 8; ++ch) {           // K 0..127 (h0): R,Z,I
                const int cb = ch * 512 + fragbase;
                uint32_t ah[4], al[4];
                {
                    uint4 vh = *(const uint4*)(shi + cb);
                    uint4 vl = *(const uint4*)(slo + cb);
                    ah[0] = vh.x; ah[1] = vh.y; ah[2] = vh.z; ah[3] = vh.w;
                    al[0] = vl.x; al[1] = vl.y; al[2] = vl.z; al[3] = vl.w;
                }
                const int gl[3] = {0, 1, 2};
#pragma unroll
                for (int gi = 0; gi < 3; ++gi) {
                    const int g = gl[gi];
#pragma unroll
                    for (int nt = 0; nt < 2; ++nt) {
                        uint4 b = g_Q1[((ch * 4 + g) * 16 + js0 + nt) * 32 + lane];
                        MMA3(acc[g][nt], ah, al, b);
                    }
                }
            }
#pragma unroll 2
            for (int ch = 8; ch < 16; ++ch) {          // K 128..255 (h1): R,Z,N
                const int cb = ch * 512 + fragbase;
                uint32_t ah[4], al[4];
                {
                    uint4 vh = *(const uint4*)(shi + cb);
                    uint4 vl = *(const uint4*)(slo + cb);
                    ah[0] = vh.x; ah[1] = vh.y; ah[2] = vh.z; ah[3] = vh.w;
                    al[0] = vl.x; al[1] = vl.y; al[2] = vl.z; al[3] = vl.w;
                }
                const int gl[3] = {0, 1, 3};
#pragma unroll
                for (int gi = 0; gi < 3; ++gi) {
                    const int g = gl[gi];
#pragma unroll
                    for (int nt = 0; nt < 2; ++nt) {
                        uint4 b = g_Q1[((ch * 4 + g) * 16 + js0 + nt) * 32 + lane];
                        MMA3(acc[g][nt], ah, al, b);
                    }
                }
            }
            // epilogue L1 (pass p)
            {
                const int hpaddr = (8 + p * 4 + wn) * 512 + fragbase;
                uint4 ph = *(const uint4*)(shi + hpaddr);
                uint4 pl = *(const uint4*)(slo + hpaddr);
                uint32_t phA[4] = {ph.x, ph.y, ph.z, ph.w};
                uint32_t plA[4] = {pl.x, pl.y, pl.z, pl.w};
                uint32_t vhi[4], vlo[4];
#pragma unroll
                for (int half = 0; half < 2; ++half) {
#pragma unroll
                    for (int nt = 0; nt < 2; ++nt) {
                        const int fi = nt * 2 + half;
                        const int jb = p * 64 + wn * 16 + nt * 8 + (lane & 3) * 2;
                        float hp[2] = { bf_lo(phA[fi]) + bf_lo(plA[fi]),
                                        bf_hi(phA[fi]) + bf_hi(plA[fi]) };
                        float h2[2];
#pragma unroll
                        for (int e = 0; e < 2; ++e) {
                            int j = jb + e;
                            int c = half * 2 + e;
                            float rr = sigf(acc[0][nt][c] + sb[512 + j]);
                            float zz = sigf(acc[1][nt][c] + sb[640 + j]);
                            float nn = tanhfast(acc[2][nt][c] + sb[768 + j] +
                                                rr * (acc[3][nt][c] + sb[896 + j]));
                            h2[e] = (1.f - zz) * nn + zz * hp[e];
                        }
                        vhi[fi] = pack_bf16x2(h2[0], h2[1], vlo[fi]);
                    }
                }
                hqh[p] = make_uint4(vhi[0], vhi[1], vhi[2], vhi[3]);
                hql[p] = make_uint4(vlo[0], vlo[1], vlo[2], vlo[3]);
            }
        }
        __syncthreads();
#pragma unroll
        for (int p = 0; p < 2; ++p) {
            const int a = (8 + p * 4 + wn) * 512 + fragbase;
            *(uint4*)(shi + a) = hqh[p];
            *(uint4*)(slo + a) = hql[p];
        }
        // no final barrier: next-step L0 touches chunks 0-7 only; readers of
        // chunks 8-15 (L1 MMA of t+1) are separated by two intervening syncs.
    }
    __syncthreads();

    // final: h1 smem -> g_h1 fp32 (16 rows x 64 col-pairs)
    for (int i = tid; i < 1024; i += 128) {
        int r = i >> 6, j = (i & 63) * 2;
        int chunk = 8 + (j >> 4);
        int jj = j & 15;
        int gr = r & 7, half = r >> 3;
        int pc = (jj >> 1) & 3, nt = jj >> 3;
        int off = chunk * 512 + (gr * 4 + pc) * 16 + (nt * 2 + half) * 4;
        uint32_t phi = *(const uint32_t*)(shi + off);
        uint32_t plo = *(const uint32_t*)(slo + off);
        float2 o = make_float2(bf_lo(phi) + bf_lo(plo), bf_hi(phi) + bf_hi(plo));
        *(float2*)(g_h1 + (size_t)(m0 + r) * TH + j) = o;
    }
}

// ---- node stage 1: LN(h1) -> xp, attention scores ----
__global__ void node_stage1(const float* __restrict__ ln_g, const float* __restrict__ ln_b,
                            const float* __restrict__ gatW,
                            const float* __restrict__ att_s, const float* __restrict__ att_d) {
    __shared__ float ts[8][TH];
    const int lane = threadIdx.x & 31, warp = threadIdx.x >> 5;
    const int m = blockIdx.x * 8 + warp;
    const float* hr = g_h1 + (size_t)m * TH;
    float v[4], s = 0.f, sq = 0.f;
#pragma unroll
    for (int i = 0; i < 4; ++i) { v[i] = hr[lane + 32 * i]; s += v[i]; sq += v[i] * v[i]; }
#pragma unroll
    for (int o = 16; o; o >>= 1) {
        s  += __shfl_xor_sync(0xffffffffu, s, o);
        sq += __shfl_xor_sync(0xffffffffu, sq, o);
    }
    float mu = s * (1.f / TH), var = sq * (1.f / TH) - mu * mu, inv = rsqrtf(var + 1e-5f);
#pragma unroll
    for (int i = 0; i < 4; ++i) {
        int k = lane + 32 * i;
        ts[warp][k] = (v[i] - mu) * inv * ln_g[k] + ln_b[k];
    }
    __syncwarp();
    float x0 = 0.f, x1 = 0.f;
#pragma unroll 4
    for (int k = 0; k < TH; ++k) {
        float tv = ts[warp][k];
        x0 = fmaf(tv, gatW[k * SH + lane], x0);
        x1 = fmaf(tv, gatW[k * SH + lane + 32], x1);
    }
    g_xp[(size_t)m * SH + lane] = x0;
    g_xp[(size_t)m * SH + lane + 32] = x1;
    float ps0 = x0 * att_s[lane], ps1 = x1 * att_s[lane + 32];
    float pd0 = x0 * att_d[lane], pd1 = x1 * att_d[lane + 32];
#pragma unroll
    for (int o = 8; o; o >>= 1) {
        ps0 += __shfl_xor_sync(0xffffffffu, ps0, o, 16);
        ps1 += __shfl_xor_sync(0xffffffffu, ps1, o, 16);
        pd0 += __shfl_xor_sync(0xffffffffu, pd0, o, 16);
        pd1 += __shfl_xor_sync(0xffffffffu, pd1, o, 16);
    }
    if ((lane & 15) == 0) {
        int h = lane >> 4;
        g_asrc[m * HEADS + h] = ps0;  g_asrc[m * HEADS + 2 + h] = ps1;
        g_adst[m * HEADS + h] = pd0;  g_adst[m * HEADS + 2 + h] = pd1;
    }
}

// ---- edge pass ----
__global__ void edge_kernel(const int* __restrict__ ei32) {
    int idx = blockIdx.x * blockDim.x + threadIdx.x;
    if (idx >= ET * HEADS) return;
    int h = idx & 3, e = idx >> 2, s, d;
    if (e < Bv * EB) {
        int g = e / EB, i = e - g * EB;
        if (g_ei_is64) { s = ei32[2 * i] + g * Nv; d = ei32[2 * (EB + i)] + g * Nv; }
        else           { s = ei32[i] + g * Nv;     d = ei32[EB + i] + g * Nv; }
    } else s = d = e - Bv * EB;
    float al = g_asrc[s * HEADS + h] + g_adst[d * HEADS + h];
    al = al > 0.f ? al : 0.2f * al;
    float ex = __expf(al);
    atomicAdd(&g_den[d * HEADS + h], ex);
    const float* xr = g_xp + (size_t)s * SH + h * 16;
    float* ar = g_agg + (size_t)d * SH + h * 16;
#pragma unroll
    for (int c = 0; c < 16; ++c) atomicAdd(&ar[c], ex * xr[c]);
}

// ---- node stage 2 ----
__global__ void node_stage2(const float* __restrict__ gat_b,
                            const float* __restrict__ ln_g, const float* __restrict__ ln_b,
                            const float* __restrict__ W1, const float* __restrict__ b1,
                            const float* __restrict__ W2, const float* __restrict__ b2,
                            float* __restrict__ out) {
    __shared__ float ys[8][SH];
    const int lane = threadIdx.x & 31, warp = threadIdx.x >> 5;
    const int m = blockIdx.x * 8 + warp;
    float s0 = g_agg[(size_t)m * SH + lane]      / g_den[m * HEADS + (lane >> 4)]     + gat_b[lane];
    float s1 = g_agg[(size_t)m * SH + lane + 32] / g_den[m * HEADS + 2 + (lane >> 4)] + gat_b[lane + 32];
    float s = s0 + s1, sq = s0 * s0 + s1 * s1;
#pragma unroll
    for (int o = 16; o; o >>= 1) {
        s  += __shfl_xor_sync(0xffffffffu, s, o);
        sq += __shfl_xor_sync(0xffffffffu, sq, o);
    }
    float mu = s * (1.f / SH), var = sq * (1.f / SH) - mu * mu, inv = rsqrtf(var + 1e-5f);
    float y0 = (s0 - mu) * inv * ln_g[lane] + ln_b[lane];
    float y1 = (s1 - mu) * inv * ln_g[lane + 32] + ln_b[lane + 32];
    y0 = y0 > 0.f ? y0 : 0.2f * y0;
    y1 = y1 > 0.f ? y1 : 0.2f * y1;
    ys[warp][lane] = y0; ys[warp][lane + 32] = y1;
    __syncwarp();
    float acc = b1[lane];
#pragma unroll
    for (int k = 0; k < SH; ++k) acc = fmaf(ys[warp][k], W1[k * 32 + lane], acc);
    acc = acc > 0.f ? acc : 0.2f * acc;
    float p = acc * W2[lane];
#pragma unroll
    for (int o = 16; o; o >>= 1) p += __shfl_xor_sync(0xffffffffu, p, o);
    if (lane == 0) out[m] = p + b2[0];
}

extern "C" void kernel_launch(void* const* d_in, const int* in_sizes, int n_in,
                              void* d_out, int out_size) {
    const float* x     = (const float*)d_in[0];
    const int*   ei32  = (const int*)d_in[1];
    const float* W_ih0 = (const float*)d_in[2];
    const float* W_hh0 = (const float*)d_in[3];
    const float* b_ih0 = (const float*)d_in[4];
    const float* b_hh0 = (const float*)d_in[5];
    const float* W_ih1 = (const float*)d_in[6];
    const float* W_hh1 = (const float*)d_in[7];
    const float* b_ih1 = (const float*)d_in[8];
    const float* b_hh1 = (const float*)d_in[9];
    const float* ln1_g = (const float*)d_in[10];
    const float* ln1_b = (const float*)d_in[11];
    const float* gat_W = (const float*)d_in[12];
    const float* att_s = (const float*)d_in[13];
    const float* att_d = (const float*)d_in[14];
    const float* gat_b = (const float*)d_in[15];
    const float* ln2_g = (const float*)d_in[16];
    const float* ln2_b = (const float*)d_in[17];
    const float* regW1 = (const float*)d_in[18];
    const float* regb1 = (const float*)d_in[19];
    const float* regW2 = (const float*)d_in[20];
    const float* regb2 = (const float*)d_in[21];
    float* out = (float*)d_out;

    cudaFuncSetAttribute(gru_all, cudaFuncAttributeMaxDynamicSharedMemorySize, SM_TOT);

    detect_ei_kernel<<<1, 256>>>(ei32);
    prep_pack<<<(Q1N + Q0N + 255) / 256, 256>>>(W_ih1, W_hh1, W_hh0);
    zero_kernel<<<2048, 512>>>();

    gru_all<<<Mn / 16, 128, SM_TOT>>>(x, W_ih0, b_ih0, b_hh0, b_ih1, b_hh1);

    node_stage1<<<Mn / 8, 256>>>(ln1_g, ln1_b, gat_W, att_s, att_d);
    edge_kernel<<<(ET * HEADS + 255) / 256, 256>>>(ei32);
    node_stage2<<<Mn / 8, 256>>>(gat_b, ln2_g, ln2_b, regW1, regb1, regW2, regb2, out);
}

// round 13
// speedup vs baseline: 1.0920x; 1.0920x over previous
#include <cuda_runtime.h>
#include <cuda_bf16.h>
#include <math.h>
#include <stdint.h>

constexpr int Bv = 16, Nv = 2000, Wv = 32, Fv = 5;
constexpr int TH = 128, SH = 64, HEADS = 4;
constexpr int Mn = Bv * Nv, EB = 32000, ET = Bv * EB + Mn;

// ---------------- device scratch ----------------
__device__ float g_h1[(size_t)Mn * TH];
__device__ float g_xp[(size_t)Mn * SH];
__device__ float g_asrc[Mn * HEADS];
__device__ float g_adst[Mn * HEADS];
__device__ float g_den[Mn * HEADS];
__device__ float g_agg[(size_t)Mn * SH];
__device__ int   g_ei_is64;
// B packs: uint4 = (bh_r0, bh_r1, bl_r0, bl_r1) per (ch, gate, jslot, lane)
constexpr int Q1N = 16 * 4 * 16 * 32;   // 32768
constexpr int Q0N = 8 * 3 * 16 * 32;    // 12288
__device__ uint4 g_Q1[Q1N];
__device__ uint4 g_Q0[Q0N];

__device__ __forceinline__ float sigf(float x) {
    return __fdividef(1.f, 1.f + __expf(-x));
}
__device__ __forceinline__ float tanhfast(float x) {
    float e = __expf(2.f * x);
    return 1.f - __fdividef(2.f, e + 1.f);
}

__device__ __forceinline__ void mma16816(float* c, const uint32_t* a,
                                         uint32_t b0, uint32_t b1) {
    asm volatile(
        "mma.sync.aligned.m16n8k16.row.col.f32.bf16.bf16.f32 "
        "{%0,%1,%2,%3}, {%4,%5,%6,%7}, {%8,%9}, {%0,%1,%2,%3};\n"
        : "+f"(c[0]), "+f"(c[1]), "+f"(c[2]), "+f"(c[3])
        : "r"(a[0]), "r"(a[1]), "r"(a[2]), "r"(a[3]), "r"(b0), "r"(b1));
}

__device__ __forceinline__ uint32_t pack_bf16x2(float f0, float f1, uint32_t& lo_out) {
    __nv_bfloat16 h0 = __float2bfloat16(f0);
    __nv_bfloat16 h1 = __float2bfloat16(f1);
    __nv_bfloat16 l0 = __float2bfloat16(f0 - __bfloat162float(h0));
    __nv_bfloat16 l1 = __float2bfloat16(f1 - __bfloat162float(h1));
    lo_out = (uint32_t)__bfloat16_as_ushort(l0) | ((uint32_t)__bfloat16_as_ushort(l1) << 16);
    return (uint32_t)__bfloat16_as_ushort(h0) | ((uint32_t)__bfloat16_as_ushort(h1) << 16);
}
__device__ __forceinline__ float bf_lo(uint32_t w) {
    return __bfloat162float(__ushort_as_bfloat16((unsigned short)(w & 0xffff)));
}
__device__ __forceinline__ float bf_hi(uint32_t w) {
    return __bfloat162float(__ushort_as_bfloat16((unsigned short)(w >> 16)));
}

// ---------------- edge-index dtype probe ----------------
__global__ void detect_ei_kernel(const int* __restrict__ w) {
    __shared__ int nz;
    if (threadIdx.x == 0) nz = 0;
    __syncthreads();
    for (int i = threadIdx.x; i < 2048; i += blockDim.x)
        if ((i & 1) && w[i] != 0) atomicOr(&nz, 1);
    __syncthreads();
    if (threadIdx.x == 0) g_ei_is64 = nz ? 0 : 1;
}

// ---------------- prep: pack weights into uint4 MMA fragments ----------------
__global__ void prep_pack(const float* __restrict__ Wih1,
                          const float* __restrict__ Whh1,
                          const float* __restrict__ Whh0) {
    int idx = blockIdx.x * blockDim.x + threadIdx.x;
    if (idx < Q1N) {
        int lane = idx & 31, js = (idx >> 5) & 15, g = (idx >> 9) & 3, ch = idx >> 11;
        int j = js * 8 + (lane >> 2);
        float v[2][2];
#pragma unroll
        for (int r = 0; r < 2; ++r) {
            int k0 = ch * 16 + (lane & 3) * 2 + r * 8;
            float a = 0.f, b = 0.f;
            if (ch < 8) {
                if (g < 3) {
                    const float* Wr = Wih1 + (size_t)(g * 128 + j) * 128;
                    a = Wr[k0]; b = Wr[k0 + 1];
                }
            } else {
                int km = k0 - 128;
                if (g != 2) {
                    int gg = (g == 3) ? 2 : g;
                    const float* Wr = Whh1 + (size_t)(gg * 128 + j) * 128;
                    a = Wr[km]; b = Wr[km + 1];
                }
            }
            v[r][0] = a; v[r][1] = b;
        }
        uint4 o;
        uint32_t lo0, lo1;
        o.x = pack_bf16x2(v[0][0], v[0][1], lo0);
        o.y = pack_bf16x2(v[1][0], v[1][1], lo1);
        o.z = lo0; o.w = lo1;
        g_Q1[idx] = o;
    } else if (idx < Q1N + Q0N) {
        int i0 = idx - Q1N;
        int lane = i0 & 31, js = (i0 >> 5) & 15;
        int rest = i0 >> 9;
        int g = rest % 3, ch = rest / 3;
        int j = js * 8 + (lane >> 2);
        const float* Wr = Whh0 + (size_t)(g * 128 + j) * 128;
        uint4 o;
        uint32_t lo0, lo1;
        int k0 = ch * 16 + (lane & 3) * 2;
        o.x = pack_bf16x2(Wr[k0], Wr[k0 + 1], lo0);
        o.y = pack_bf16x2(Wr[k0 + 8], Wr[k0 + 9], lo1);
        o.z = lo0; o.w = lo1;
        g_Q0[i0] = o;
    }
}

__global__ void zero_kernel() {
    size_t stride = (size_t)gridDim.x * blockDim.x;
    for (size_t i = (size_t)blockIdx.x * blockDim.x + threadIdx.x;
         i < (size_t)Mn * SH; i += stride) {
        g_agg[i] = 0.f;
        if (i < (size_t)Mn * HEADS) g_den[i] = 0.f;
    }
}

#define MMA3(accp, ahv, alv, bq)              \
    mma16816(accp, ahv, (bq).x, (bq).y);      \
    mma16816(accp, alv, (bq).x, (bq).y);      \
    mma16816(accp, ahv, (bq).z, (bq).w);

// ===== persistent GRU: grid 1000 (M=32 tiles), block 128 (4 warps), 4 CTAs/SM =====
// smem: state hi[16*1024] | lo[16*1024] | sW[1920 f] | sb[1024 f] | sX[160 f]
constexpr int SM_SLO = 16384;
constexpr int SM_SW  = 32768;
constexpr int SM_SB  = SM_SW + 7680;
constexpr int SM_SX  = SM_SB + 4096;
constexpr int SM_TOT = SM_SX + 640;      // 45184

__global__ __launch_bounds__(128, 4)
void gru_all(const float* __restrict__ X, const float* __restrict__ Wih0,
             const float* __restrict__ bi0, const float* __restrict__ bh0,
             const float* __restrict__ bi1, const float* __restrict__ bh1) {
    extern __shared__ char sm[];
    char* shi = sm;
    char* slo = sm + SM_SLO;
    float* sW = (float*)(sm + SM_SW);
    float* sb = (float*)(sm + SM_SB);
    float* sX = (float*)(sm + SM_SX);

    const int tid = threadIdx.x, lane = tid & 31, wn = tid >> 5;   // wn = warp 0..3
    const int m0 = blockIdx.x * 32;
    const int fragbase = lane * 16;

    {
        uint4 z = make_uint4(0, 0, 0, 0);
        for (int i = tid; i < 1024; i += 128) {
            ((uint4*)shi)[i] = z;
            ((uint4*)slo)[i] = z;
        }
    }
    for (int i = tid; i < 384 * Fv; i += 128) sW[i] = Wih0[i];
    for (int i = tid; i < 1024; i += 128) {
        int j = i & 127, which = (i >> 7) & 3, L = i >> 9;
        const float* BI = L ? bi1 : bi0;
        const float* BH = L ? bh1 : bh0;
        float v;
        if (which == 0)      v = BI[j] + BH[j];
        else if (which == 1) v = BI[128 + j] + BH[128 + j];
        else if (which == 2) v = BI[256 + j];
        else                 v = BH[256 + j];
        sb[i] = v;
    }
    __syncthreads();

    for (int t = 0; t < Wv; ++t) {
        uint4 hqh[2][2], hql[2][2];   // [pass][mi]

        // X prefetch (each warp writes all 160 -> reads its own writes)
        for (int i = lane; i < 160; i += 32) {
            int rr = i / 5, f = i - rr * 5;
            sX[i] = X[((size_t)(m0 + rr) * Wv + t) * Fv + f];
        }
        __syncwarp();

        // ================= LAYER 0 =================
        for (int p = 0; p < 2; ++p) {
            float acc[3][2][2][4];
#pragma unroll
            for (int g = 0; g < 3; ++g)
#pragma unroll
                for (int nt = 0; nt < 2; ++nt)
#pragma unroll
                    for (int mi = 0; mi < 2; ++mi)
#pragma unroll
                        for (int e = 0; e < 4; ++e) acc[g][nt][mi][e] = 0.f;
            const int js0 = p * 8 + wn * 2;
#pragma unroll 2
            for (int ch = 0; ch < 8; ++ch) {
                const int cb = ch * 1024 + fragbase;
                uint32_t ah[2][4], al[2][4];
#pragma unroll
                for (int mi = 0; mi < 2; ++mi) {
                    uint4 vh = *(const uint4*)(shi + cb + mi * 512);
                    uint4 vl = *(const uint4*)(slo + cb + mi * 512);
                    ah[mi][0] = vh.x; ah[mi][1] = vh.y; ah[mi][2] = vh.z; ah[mi][3] = vh.w;
                    al[mi][0] = vl.x; al[mi][1] = vl.y; al[mi][2] = vl.z; al[mi][3] = vl.w;
                }
#pragma unroll
                for (int g = 0; g < 3; ++g)
#pragma unroll
                    for (int nt = 0; nt < 2; ++nt) {
                        uint4 b = g_Q0[((ch * 3 + g) * 16 + js0 + nt) * 32 + lane];
#pragma unroll
                        for (int mi = 0; mi < 2; ++mi) { MMA3(acc[g][nt][mi], ah[mi], al[mi], b); }
                    }
            }
            // epilogue L0 (pass p)
#pragma unroll
            for (int mi = 0; mi < 2; ++mi) {
                const int hpaddr = (p * 4 + wn) * 1024 + fragbase + mi * 512;
                uint4 ph = *(const uint4*)(shi + hpaddr);
                uint4 pl = *(const uint4*)(slo + hpaddr);
                uint32_t phA[4] = {ph.x, ph.y, ph.z, ph.w};
                uint32_t plA[4] = {pl.x, pl.y, pl.z, pl.w};
                uint32_t vhi[4], vlo[4];
#pragma unroll
                for (int half = 0; half < 2; ++half) {
                    const int r = mi * 16 + (lane >> 2) + half * 8;
                    float xv[Fv];
#pragma unroll
                    for (int f = 0; f < Fv; ++f) xv[f] = sX[r * 5 + f];
#pragma unroll
                    for (int nt = 0; nt < 2; ++nt) {
                        const int fi = nt * 2 + half;
                        const int jb = p * 64 + wn * 16 + nt * 8 + (lane & 3) * 2;
                        float hp[2] = { bf_lo(phA[fi]) + bf_lo(plA[fi]),
                                        bf_hi(phA[fi]) + bf_hi(plA[fi]) };
                        float h2[2];
#pragma unroll
                        for (int e = 0; e < 2; ++e) {
                            int j = jb + e;
                            float sR = 0.f, sZ = 0.f, sI = 0.f;
#pragma unroll
                            for (int f = 0; f < Fv; ++f) {
                                sR = fmaf(xv[f], sW[j * Fv + f], sR);
                                sZ = fmaf(xv[f], sW[(128 + j) * Fv + f], sZ);
                                sI = fmaf(xv[f], sW[(256 + j) * Fv + f], sI);
                            }
                            int c = half * 2 + e;
                            float rr = sigf(acc[0][nt][mi][c] + sR + sb[j]);
                            float zz = sigf(acc[1][nt][mi][c] + sZ + sb[128 + j]);
                            float nn = tanhfast(sI + sb[256 + j] +
                                                rr * (acc[2][nt][mi][c] + sb[384 + j]));
                            h2[e] = (1.f - zz) * nn + zz * hp[e];
                        }
                        vhi[fi] = pack_bf16x2(h2[0], h2[1], vlo[fi]);
                    }
                }
                hqh[p][mi] = make_uint4(vhi[0], vhi[1], vhi[2], vhi[3]);
                hql[p][mi] = make_uint4(vlo[0], vlo[1], vlo[2], vlo[3]);
            }
        }
        __syncthreads();
#pragma unroll
        for (int p = 0; p < 2; ++p)
#pragma unroll
            for (int mi = 0; mi < 2; ++mi) {
                const int a = (p * 4 + wn) * 1024 + fragbase + mi * 512;
                *(uint4*)(shi + a) = hqh[p][mi];
                *(uint4*)(slo + a) = hql[p][mi];
            }
        __syncthreads();

        // ================= LAYER 1 =================
        for (int p = 0; p < 2; ++p) {
            float acc[4][2][2][4];
#pragma unroll
            for (int g = 0; g < 4; ++g)
#pragma unroll
                for (int nt = 0; nt < 2; ++nt)
#pragma unroll
                    for (int mi = 0; mi < 2; ++mi)
#pragma unroll
                        for (int e = 0; e < 4; ++e) acc[g][nt][mi][e] = 0.f;
            const int js0 = p * 8 + wn * 2;
#pragma unroll 2
            for (int ch = 0; ch < 8; ++ch) {           // K 0..127 (h0): R,Z,I
                const int cb = ch * 1024 + fragbase;
                uint32_t ah[2][4], al[2][4];
#pragma unroll
                for (int mi = 0; mi < 2; ++mi) {
                    uint4 vh = *(const uint4*)(shi + cb + mi * 512);
                    uint4 vl = *(const uint4*)(slo + cb + mi * 512);
                    ah[mi][0] = vh.x; ah[mi][1] = vh.y; ah[mi][2] = vh.z; ah[mi][3] = vh.w;
                    al[mi][0] = vl.x; al[mi][1] = vl.y; al[mi][2] = vl.z; al[mi][3] = vl.w;
                }
                const int gl[3] = {0, 1, 2};
#pragma unroll
                for (int gi = 0; gi < 3; ++gi) {
                    const int g = gl[gi];
#pragma unroll
                    for (int nt = 0; nt < 2; ++nt) {
                        uint4 b = g_Q1[((ch * 4 + g) * 16 + js0 + nt) * 32 + lane];
#pragma unroll
                        for (int mi = 0; mi < 2; ++mi) { MMA3(acc[g][nt][mi], ah[mi], al[mi], b); }
                    }
                }
            }
#pragma unroll 2
            for (int ch = 8; ch < 16; ++ch) {          // K 128..255 (h1): R,Z,N
                const int cb = ch * 1024 + fragbase;
                uint32_t ah[2][4], al[2][4];
#pragma unroll
                for (int mi = 0; mi < 2; ++mi) {
                    uint4 vh = *(const uint4*)(shi + cb + mi * 512);
                    uint4 vl = *(const uint4*)(slo + cb + mi * 512);
                    ah[mi][0] = vh.x; ah[mi][1] = vh.y; ah[mi][2] = vh.z; ah[mi][3] = vh.w;
                    al[mi][0] = vl.x; al[mi][1] = vl.y; al[mi][2] = vl.z; al[mi][3] = vl.w;
                }
                const int gl[3] = {0, 1, 3};
#pragma unroll
                for (int gi = 0; gi < 3; ++gi) {
                    const int g = gl[gi];
#pragma unroll
                    for (int nt = 0; nt < 2; ++nt) {
                        uint4 b = g_Q1[((ch * 4 + g) * 16 + js0 + nt) * 32 + lane];
#pragma unroll
                        for (int mi = 0; mi < 2; ++mi) { MMA3(acc[g][nt][mi], ah[mi], al[mi], b); }
                    }
                }
            }
            // epilogue L1 (pass p)
#pragma unroll
            for (int mi = 0; mi < 2; ++mi) {
                const int hpaddr = (8 + p * 4 + wn) * 1024 + fragbase + mi * 512;
                uint4 ph = *(const uint4*)(shi + hpaddr);
                uint4 pl = *(const uint4*)(slo + hpaddr);
                uint32_t phA[4] = {ph.x, ph.y, ph.z, ph.w};
                uint32_t plA[4] = {pl.x, pl.y, pl.z, pl.w};
                uint32_t vhi[4], vlo[4];
#pragma unroll
                for (int half = 0; half < 2; ++half) {
#pragma unroll
                    for (int nt = 0; nt < 2; ++nt) {
                        const int fi = nt * 2 + half;
                        const int jb = p * 64 + wn * 16 + nt * 8 + (lane & 3) * 2;
                        float hp[2] = { bf_lo(phA[fi]) + bf_lo(plA[fi]),
                                        bf_hi(phA[fi]) + bf_hi(plA[fi]) };
                        float h2[2];
#pragma unroll
                        for (int e = 0; e < 2; ++e) {
                            int j = jb + e;
                            int c = half * 2 + e;
                            float rr = sigf(acc[0][nt][mi][c] + sb[512 + j]);
                            float zz = sigf(acc[1][nt][mi][c] + sb[640 + j]);
                            float nn = tanhfast(acc[2][nt][mi][c] + sb[768 + j] +
                                                rr * (acc[3][nt][mi][c] + sb[896 + j]));
                            h2[e] = (1.f - zz) * nn + zz * hp[e];
                        }
                        vhi[fi] = pack_bf16x2(h2[0], h2[1], vlo[fi]);
                    }
                }
                hqh[p][mi] = make_uint4(vhi[0], vhi[1], vhi[2], vhi[3]);
                hql[p][mi] = make_uint4(vlo[0], vlo[1], vlo[2], vlo[3]);
            }
        }
        __syncthreads();
#pragma unroll
        for (int p = 0; p < 2; ++p)
#pragma unroll
            for (int mi = 0; mi < 2; ++mi) {
                const int a = (8 + p * 4 + wn) * 1024 + fragbase + mi * 512;
                *(uint4*)(shi + a) = hqh[p][mi];
                *(uint4*)(slo + a) = hql[p][mi];
            }
        // no barrier here (redundant): next-step L0 touches only chunks 0-7 +
        // sX; every reader of chunks 8-15 (L1 MMA of t+1, per-warp-own L1
        // epilogue hp) is separated from this STS by the two syncs above.
    }
    __syncthreads();

    // final: h1 smem -> g_h1 fp32 (32 rows x 64 col-pairs)
    for (int i = tid; i < 2048; i += 128) {
        int r = i >> 6, j = (i & 63) * 2;
        int chunk = 8 + ((i & 63) >> 3);
        int q = i & 7, pc = q & 3, nt = q >> 2;
        int gr = r & 7, half = (r >> 3) & 1, mi = r >> 4;
        int off = chunk * 1024 + mi * 512 + (gr * 4 + pc) * 16 + (nt * 2 + half) * 4;
        uint32_t phi = *(const uint32_t*)(shi + off);
        uint32_t plo = *(const uint32_t*)(slo + off);
        float2 o = make_float2(bf_lo(phi) + bf_lo(plo), bf_hi(phi) + bf_hi(plo));
        *(float2*)(g_h1 + (size_t)(m0 + r) * TH + j) = o;
    }
}

// ---- node stage 1: LN(h1) -> xp, attention scores ----
__global__ void node_stage1(const float* __restrict__ ln_g, const float* __restrict__ ln_b,
                            const float* __restrict__ gatW,
                            const float* __restrict__ att_s, const float* __restrict__ att_d) {
    __shared__ float ts[8][TH];
    const int lane = threadIdx.x & 31, warp = threadIdx.x >> 5;
    const int m = blockIdx.x * 8 + warp;
    const float* hr = g_h1 + (size_t)m * TH;
    float v[4], s = 0.f, sq = 0.f;
#pragma unroll
    for (int i = 0; i < 4; ++i) { v[i] = hr[lane + 32 * i]; s += v[i]; sq += v[i] * v[i]; }
#pragma unroll
    for (int o = 16; o; o >>= 1) {
        s  += __shfl_xor_sync(0xffffffffu, s, o);
        sq += __shfl_xor_sync(0xffffffffu, sq, o);
    }
    float mu = s * (1.f / TH), var = sq * (1.f / TH) - mu * mu, inv = rsqrtf(var + 1e-5f);
#pragma unroll
    for (int i = 0; i < 4; ++i) {
        int k = lane + 32 * i;
        ts[warp][k] = (v[i] - mu) * inv * ln_g[k] + ln_b[k];
    }
    __syncwarp();
    float x0 = 0.f, x1 = 0.f;
#pragma unroll 4
    for (int k = 0; k < TH; ++k) {
        float tv = ts[warp][k];
        x0 = fmaf(tv, gatW[k * SH + lane], x0);
        x1 = fmaf(tv, gatW[k * SH + lane + 32], x1);
    }
    g_xp[(size_t)m * SH + lane] = x0;
    g_xp[(size_t)m * SH + lane + 32] = x1;
    float ps0 = x0 * att_s[lane], ps1 = x1 * att_s[lane + 32];
    float pd0 = x0 * att_d[lane], pd1 = x1 * att_d[lane + 32];
#pragma unroll
    for (int o = 8; o; o >>= 1) {
        ps0 += __shfl_xor_sync(0xffffffffu, ps0, o, 16);
        ps1 += __shfl_xor_sync(0xffffffffu, ps1, o, 16);
        pd0 += __shfl_xor_sync(0xffffffffu, pd0, o, 16);
        pd1 += __shfl_xor_sync(0xffffffffu, pd1, o, 16);
    }
    if ((lane & 15) == 0) {
        int h = lane >> 4;
        g_asrc[m * HEADS + h] = ps0;  g_asrc[m * HEADS + 2 + h] = ps1;
        g_adst[m * HEADS + h] = pd0;  g_adst[m * HEADS + 2 + h] = pd1;
    }
}

// ---- edge pass ----
__global__ void edge_kernel(const int* __restrict__ ei32) {
    int idx = blockIdx.x * blockDim.x + threadIdx.x;
    if (idx >= ET * HEADS) return;
    int h = idx & 3, e = idx >> 2, s, d;
    if (e < Bv * EB) {
        int g = e / EB, i = e - g * EB;
        if (g_ei_is64) { s = ei32[2 * i] + g * Nv; d = ei32[2 * (EB + i)] + g * Nv; }
        else           { s = ei32[i] + g * Nv;     d = ei32[EB + i] + g * Nv; }
    } else s = d = e - Bv * EB;
    float al = g_asrc[s * HEADS + h] + g_adst[d * HEADS + h];
    al = al > 0.f ? al : 0.2f * al;
    float ex = __expf(al);
    atomicAdd(&g_den[d * HEADS + h], ex);
    const float* xr = g_xp + (size_t)s * SH + h * 16;
    float* ar = g_agg + (size_t)d * SH + h * 16;
#pragma unroll
    for (int c = 0; c < 16; ++c) atomicAdd(&ar[c], ex * xr[c]);
}

// ---- node stage 2 ----
__global__ void node_stage2(const float* __restrict__ gat_b,
                            const float* __restrict__ ln_g, const float* __restrict__ ln_b,
                            const float* __restrict__ W1, const float* __restrict__ b1,
                            const float* __restrict__ W2, const float* __restrict__ b2,
                            float* __restrict__ out) {
    __shared__ float ys[8][SH];
    const int lane = threadIdx.x & 31, warp = threadIdx.x >> 5;
    const int m = blockIdx.x * 8 + warp;
    float s0 = g_agg[(size_t)m * SH + lane]      / g_den[m * HEADS + (lane >> 4)]     + gat_b[lane];
    float s1 = g_agg[(size_t)m * SH + lane + 32] / g_den[m * HEADS + 2 + (lane >> 4)] + gat_b[lane + 32];
    float s = s0 + s1, sq = s0 * s0 + s1 * s1;
#pragma unroll
    for (int o = 16; o; o >>= 1) {
        s  += __shfl_xor_sync(0xffffffffu, s, o);
        sq += __shfl_xor_sync(0xffffffffu, sq, o);
    }
    float mu = s * (1.f / SH), var = sq * (1.f / SH) - mu * mu, inv = rsqrtf(var + 1e-5f);
    float y0 = (s0 - mu) * inv * ln_g[lane] + ln_b[lane];
    float y1 = (s1 - mu) * inv * ln_g[lane + 32] + ln_b[lane + 32];
    y0 = y0 > 0.f ? y0 : 0.2f * y0;
    y1 = y1 > 0.f ? y1 : 0.2f * y1;
    ys[warp][lane] = y0; ys[warp][lane + 32] = y1;
    __syncwarp();
    float acc = b1[lane];
#pragma unroll
    for (int k = 0; k < SH; ++k) acc = fmaf(ys[warp][k], W1[k * 32 + lane], acc);
    acc = acc > 0.f ? acc : 0.2f * acc;
    float p = acc * W2[lane];
#pragma unroll
    for (int o = 16; o; o >>= 1) p += __shfl_xor_sync(0xffffffffu, p, o);
    if (lane == 0) out[m] = p + b2[0];
}

extern "C" void kernel_launch(void* const* d_in, const int* in_sizes, int n_in,
                              void* d_out, int out_size) {
    const float* x     = (const float*)d_in[0];
    const int*   ei32  = (const int*)d_in[1];
    const float* W_ih0 = (const float*)d_in[2];
    const float* W_hh0 = (const float*)d_in[3];
    const float* b_ih0 = (const float*)d_in[4];
    const float* b_hh0 = (const float*)d_in[5];
    const float* W_ih1 = (const float*)d_in[6];
    const float* W_hh1 = (const float*)d_in[7];
    const float* b_ih1 = (const float*)d_in[8];
    const float* b_hh1 = (const float*)d_in[9];
    const float* ln1_g = (const float*)d_in[10];
    const float* ln1_b = (const float*)d_in[11];
    const float* gat_W = (const float*)d_in[12];
    const float* att_s = (const float*)d_in[13];
    const float* att_d = (const float*)d_in[14];
    const float* gat_b = (const float*)d_in[15];
    const float* ln2_g = (const float*)d_in[16];
    const float* ln2_b = (const float*)d_in[17];
    const float* regW1 = (const float*)d_in[18];
    const float* regb1 = (const float*)d_in[19];
    const float* regW2 = (const float*)d_in[20];
    const float* regb2 = (const float*)d_in[21];
    float* out = (float*)d_out;

    cudaFuncSetAttribute(gru_all, cudaFuncAttributeMaxDynamicSharedMemorySize, SM_TOT);

    detect_ei_kernel<<<1, 256>>>(ei32);
    prep_pack<<<(Q1N + Q0N + 255) / 256, 256>>>(W_ih1, W_hh1, W_hh0);
    zero_kernel<<<2048, 512>>>();

    gru_all<<<Mn / 32, 128, SM_TOT>>>(x, W_ih0, b_ih0, b_hh0, b_ih1, b_hh1);

    node_stage1<<<Mn / 8, 256>>>(ln1_g, ln1_b, gat_W, att_s, att_d);
    edge_kernel<<<(ET * HEADS + 255) / 256, 256>>>(ei32);
    node_stage2<<<Mn / 8, 256>>>(gat_b, ln2_g, ln2_b, regW1, regb1, regW2, regb2, out);
}

// round 14
// speedup vs baseline: 1.1434x; 1.0471x over previous
#include <cuda_runtime.h>
#include <cuda_bf16.h>
#include <math.h>
#include <stdint.h>

constexpr int Bv = 16, Nv = 2000, Wv = 32, Fv = 5;
constexpr int TH = 128, SH = 64, HEADS = 4;
constexpr int Mn = Bv * Nv, EB = 32000, ET = Bv * EB + Mn;

// ---------------- device scratch ----------------
__device__ float g_h1[(size_t)Mn * TH];
__device__ float g_xp[(size_t)Mn * SH];
__device__ float g_asrc[Mn * HEADS];
__device__ float g_adst[Mn * HEADS];
__device__ float g_den[Mn * HEADS];
__device__ float g_agg[(size_t)Mn * SH];
__device__ int   g_ei_is64;
// B packs: uint4 = (bh_r0, bh_r1, bl_r0, bl_r1) per (ch, gate, jslot, lane)
constexpr int Q1N = 16 * 4 * 16 * 32;   // 32768
constexpr int Q0N = 8 * 3 * 16 * 32;    // 12288
__device__ uint4 g_Q1[Q1N];
__device__ uint4 g_Q0[Q0N];

__device__ __forceinline__ float sigf(float x) {
    return __fdividef(1.f, 1.f + __expf(-x));
}
__device__ __forceinline__ float tanhfast(float x) {
    float e = __expf(2.f * x);
    return 1.f - __fdividef(2.f, e + 1.f);
}

__device__ __forceinline__ void mma16816(float* c, const uint32_t* a,
                                         uint32_t b0, uint32_t b1) {
    asm volatile(
        "mma.sync.aligned.m16n8k16.row.col.f32.bf16.bf16.f32 "
        "{%0,%1,%2,%3}, {%4,%5,%6,%7}, {%8,%9}, {%0,%1,%2,%3};\n"
        : "+f"(c[0]), "+f"(c[1]), "+f"(c[2]), "+f"(c[3])
        : "r"(a[0]), "r"(a[1]), "r"(a[2]), "r"(a[3]), "r"(b0), "r"(b1));
}

__device__ __forceinline__ uint32_t pack_bf16x2(float f0, float f1, uint32_t& lo_out) {
    __nv_bfloat16 h0 = __float2bfloat16(f0);
    __nv_bfloat16 h1 = __float2bfloat16(f1);
    __nv_bfloat16 l0 = __float2bfloat16(f0 - __bfloat162float(h0));
    __nv_bfloat16 l1 = __float2bfloat16(f1 - __bfloat162float(h1));
    lo_out = (uint32_t)__bfloat16_as_ushort(l0) | ((uint32_t)__bfloat16_as_ushort(l1) << 16);
    return (uint32_t)__bfloat16_as_ushort(h0) | ((uint32_t)__bfloat16_as_ushort(h1) << 16);
}
__device__ __forceinline__ float bf_lo(uint32_t w) {
    return __bfloat162float(__ushort_as_bfloat16((unsigned short)(w & 0xffff)));
}
__device__ __forceinline__ float bf_hi(uint32_t w) {
    return __bfloat162float(__ushort_as_bfloat16((unsigned short)(w >> 16)));
}

// vectorized global reduction (sm_90+, PTX ISA 8.1)
__device__ __forceinline__ void red_add_v4(float* addr, float a, float b,
                                           float c, float d) {
    asm volatile("red.global.add.v4.f32 [%0], {%1, %2, %3, %4};"
                 :: "l"(addr), "f"(a), "f"(b), "f"(c), "f"(d) : "memory");
}

// ---------------- edge-index dtype probe ----------------
__global__ void detect_ei_kernel(const int* __restrict__ w) {
    __shared__ int nz;
    if (threadIdx.x == 0) nz = 0;
    __syncthreads();
    for (int i = threadIdx.x; i < 2048; i += blockDim.x)
        if ((i & 1) && w[i] != 0) atomicOr(&nz, 1);
    __syncthreads();
    if (threadIdx.x == 0) g_ei_is64 = nz ? 0 : 1;
}

// ---------------- prep: pack weights into uint4 MMA fragments ----------------
__global__ void prep_pack(const float* __restrict__ Wih1,
                          const float* __restrict__ Whh1,
                          const float* __restrict__ Whh0) {
    int idx = blockIdx.x * blockDim.x + threadIdx.x;
    if (idx < Q1N) {
        int lane = idx & 31, js = (idx >> 5) & 15, g = (idx >> 9) & 3, ch = idx >> 11;
        int j = js * 8 + (lane >> 2);
        float v[2][2];
#pragma unroll
        for (int r = 0; r < 2; ++r) {
            int k0 = ch * 16 + (lane & 3) * 2 + r * 8;
            float a = 0.f, b = 0.f;
            if (ch < 8) {
                if (g < 3) {
                    const float* Wr = Wih1 + (size_t)(g * 128 + j) * 128;
                    a = Wr[k0]; b = Wr[k0 + 1];
                }
            } else {
                int km = k0 - 128;
                if (g != 2) {
                    int gg = (g == 3) ? 2 : g;
                    const float* Wr = Whh1 + (size_t)(gg * 128 + j) * 128;
                    a = Wr[km]; b = Wr[km + 1];
                }
            }
            v[r][0] = a; v[r][1] = b;
        }
        uint4 o;
        uint32_t lo0, lo1;
        o.x = pack_bf16x2(v[0][0], v[0][1], lo0);
        o.y = pack_bf16x2(v[1][0], v[1][1], lo1);
        o.z = lo0; o.w = lo1;
        g_Q1[idx] = o;
    } else if (idx < Q1N + Q0N) {
        int i0 = idx - Q1N;
        int lane = i0 & 31, js = (i0 >> 5) & 15;
        int rest = i0 >> 9;
        int g = rest % 3, ch = rest / 3;
        int j = js * 8 + (lane >> 2);
        const float* Wr = Whh0 + (size_t)(g * 128 + j) * 128;
        uint4 o;
        uint32_t lo0, lo1;
        int k0 = ch * 16 + (lane & 3) * 2;
        o.x = pack_bf16x2(Wr[k0], Wr[k0 + 1], lo0);
        o.y = pack_bf16x2(Wr[k0 + 8], Wr[k0 + 9], lo1);
        o.z = lo0; o.w = lo1;
        g_Q0[i0] = o;
    }
}

__global__ void zero_kernel() {
    size_t stride = (size_t)gridDim.x * blockDim.x;
    for (size_t i = (size_t)blockIdx.x * blockDim.x + threadIdx.x;
         i < (size_t)Mn * SH; i += stride) {
        g_agg[i] = 0.f;
        if (i < (size_t)Mn * HEADS) g_den[i] = 0.f;
    }
}

#define MMA3(accp, ahv, alv, bq)              \
    mma16816(accp, ahv, (bq).x, (bq).y);      \
    mma16816(accp, alv, (bq).x, (bq).y);      \
    mma16816(accp, ahv, (bq).z, (bq).w);

// ===== persistent GRU: grid 1000 (M=32 tiles), block 128 (4 warps), 4 CTAs/SM =====
// smem: state hi[16*1024] | lo[16*1024] | sW[1920 f] | sb[1024 f] | sX[160 f]
constexpr int SM_SLO = 16384;
constexpr int SM_SW  = 32768;
constexpr int SM_SB  = SM_SW + 7680;
constexpr int SM_SX  = SM_SB + 4096;
constexpr int SM_TOT = SM_SX + 640;      // 45184

__global__ __launch_bounds__(128, 4)
void gru_all(const float* __restrict__ X, const float* __restrict__ Wih0,
             const float* __restrict__ bi0, const float* __restrict__ bh0,
             const float* __restrict__ bi1, const float* __restrict__ bh1) {
    extern __shared__ char sm[];
    char* shi = sm;
    char* slo = sm + SM_SLO;
    float* sW = (float*)(sm + SM_SW);
    float* sb = (float*)(sm + SM_SB);
    float* sX = (float*)(sm + SM_SX);

    const int tid = threadIdx.x, lane = tid & 31, wn = tid >> 5;   // wn = warp 0..3
    const int m0 = blockIdx.x * 32;
    const int fragbase = lane * 16;

    {
        uint4 z = make_uint4(0, 0, 0, 0);
        for (int i = tid; i < 1024; i += 128) {
            ((uint4*)shi)[i] = z;
            ((uint4*)slo)[i] = z;
        }
    }
    for (int i = tid; i < 384 * Fv; i += 128) sW[i] = Wih0[i];
    for (int i = tid; i < 1024; i += 128) {
        int j = i & 127, which = (i >> 7) & 3, L = i >> 9;
        const float* BI = L ? bi1 : bi0;
        const float* BH = L ? bh1 : bh0;
        float v;
        if (which == 0)      v = BI[j] + BH[j];
        else if (which == 1) v = BI[128 + j] + BH[128 + j];
        else if (which == 2) v = BI[256 + j];
        else                 v = BH[256 + j];
        sb[i] = v;
    }
    __syncthreads();

    for (int t = 0; t < Wv; ++t) {
        uint4 hqh[2][2], hql[2][2];   // [pass][mi]

        // X prefetch (each warp writes all 160 -> reads its own writes)
        for (int i = lane; i < 160; i += 32) {
            int rr = i / 5, f = i - rr * 5;
            sX[i] = X[((size_t)(m0 + rr) * Wv + t) * Fv + f];
        }
        __syncwarp();

        // ================= LAYER 0 =================
        for (int p = 0; p < 2; ++p) {
            float acc[3][2][2][4];
#pragma unroll
            for (int g = 0; g < 3; ++g)
#pragma unroll
                for (int nt = 0; nt < 2; ++nt)
#pragma unroll
                    for (int mi = 0; mi < 2; ++mi)
#pragma unroll
                        for (int e = 0; e < 4; ++e) acc[g][nt][mi][e] = 0.f;
            const int js0 = p * 8 + wn * 2;
#pragma unroll 2
            for (int ch = 0; ch < 8; ++ch) {
                const int cb = ch * 1024 + fragbase;
                uint32_t ah[2][4], al[2][4];
#pragma unroll
                for (int mi = 0; mi < 2; ++mi) {
                    uint4 vh = *(const uint4*)(shi + cb + mi * 512);
                    uint4 vl = *(const uint4*)(slo + cb + mi * 512);
                    ah[mi][0] = vh.x; ah[mi][1] = vh.y; ah[mi][2] = vh.z; ah[mi][3] = vh.w;
                    al[mi][0] = vl.x; al[mi][1] = vl.y; al[mi][2] = vl.z; al[mi][3] = vl.w;
                }
#pragma unroll
                for (int g = 0; g < 3; ++g)
#pragma unroll
                    for (int nt = 0; nt < 2; ++nt) {
                        uint4 b = g_Q0[((ch * 3 + g) * 16 + js0 + nt) * 32 + lane];
#pragma unroll
                        for (int mi = 0; mi < 2; ++mi) { MMA3(acc[g][nt][mi], ah[mi], al[mi], b); }
                    }
            }
            // epilogue L0 (pass p)
#pragma unroll
            for (int mi = 0; mi < 2; ++mi) {
                const int hpaddr = (p * 4 + wn) * 1024 + fragbase + mi * 512;
                uint4 ph = *(const uint4*)(shi + hpaddr);
                uint4 pl = *(const uint4*)(slo + hpaddr);
                uint32_t phA[4] = {ph.x, ph.y, ph.z, ph.w};
                uint32_t plA[4] = {pl.x, pl.y, pl.z, pl.w};
                uint32_t vhi[4], vlo[4];
#pragma unroll
                for (int half = 0; half < 2; ++half) {
                    const int r = mi * 16 + (lane >> 2) + half * 8;
                    float xv[Fv];
#pragma unroll
                    for (int f = 0; f < Fv; ++f) xv[f] = sX[r * 5 + f];
#pragma unroll
                    for (int nt = 0; nt < 2; ++nt) {
                        const int fi = nt * 2 + half;
                        const int jb = p * 64 + wn * 16 + nt * 8 + (lane & 3) * 2;
                        float hp[2] = { bf_lo(phA[fi]) + bf_lo(plA[fi]),
                                        bf_hi(phA[fi]) + bf_hi(plA[fi]) };
                        float h2[2];
#pragma unroll
                        for (int e = 0; e < 2; ++e) {
                            int j = jb + e;
                            float sR = 0.f, sZ = 0.f, sI = 0.f;
#pragma unroll
                            for (int f = 0; f < Fv; ++f) {
                                sR = fmaf(xv[f], sW[j * Fv + f], sR);
                                sZ = fmaf(xv[f], sW[(128 + j) * Fv + f], sZ);
                                sI = fmaf(xv[f], sW[(256 + j) * Fv + f], sI);
                            }
                            int c = half * 2 + e;
                            float rr = sigf(acc[0][nt][mi][c] + sR + sb[j]);
                            float zz = sigf(acc[1][nt][mi][c] + sZ + sb[128 + j]);
                            float nn = tanhfast(sI + sb[256 + j] +
                                                rr * (acc[2][nt][mi][c] + sb[384 + j]));
                            h2[e] = (1.f - zz) * nn + zz * hp[e];
                        }
                        vhi[fi] = pack_bf16x2(h2[0], h2[1], vlo[fi]);
                    }
                }
                hqh[p][mi] = make_uint4(vhi[0], vhi[1], vhi[2], vhi[3]);
                hql[p][mi] = make_uint4(vlo[0], vlo[1], vlo[2], vlo[3]);
            }
        }
        __syncthreads();
#pragma unroll
        for (int p = 0; p < 2; ++p)
#pragma unroll
            for (int mi = 0; mi < 2; ++mi) {
                const int a = (p * 4 + wn) * 1024 + fragbase + mi * 512;
                *(uint4*)(shi + a) = hqh[p][mi];
                *(uint4*)(slo + a) = hql[p][mi];
            }
        __syncthreads();

        // ================= LAYER 1 =================
        for (int p = 0; p < 2; ++p) {
            float acc[4][2][2][4];
#pragma unroll
            for (int g = 0; g < 4; ++g)
#pragma unroll
                for (int nt = 0; nt < 2; ++nt)
#pragma unroll
                    for (int mi = 0; mi < 2; ++mi)
#pragma unroll
                        for (int e = 0; e < 4; ++e) acc[g][nt][mi][e] = 0.f;
            const int js0 = p * 8 + wn * 2;
#pragma unroll 2
            for (int ch = 0; ch < 8; ++ch) {           // K 0..127 (h0): R,Z,I
                const int cb = ch * 1024 + fragbase;
                uint32_t ah[2][4], al[2][4];
#pragma unroll
                for (int mi = 0; mi < 2; ++mi) {
                    uint4 vh = *(const uint4*)(shi + cb + mi * 512);
                    uint4 vl = *(const uint4*)(slo + cb + mi * 512);
                    ah[mi][0] = vh.x; ah[mi][1] = vh.y; ah[mi][2] = vh.z; ah[mi][3] = vh.w;
                    al[mi][0] = vl.x; al[mi][1] = vl.y; al[mi][2] = vl.z; al[mi][3] = vl.w;
                }
                const int gl[3] = {0, 1, 2};
#pragma unroll
                for (int gi = 0; gi < 3; ++gi) {
                    const int g = gl[gi];
#pragma unroll
                    for (int nt = 0; nt < 2; ++nt) {
                        uint4 b = g_Q1[((ch * 4 + g) * 16 + js0 + nt) * 32 + lane];
#pragma unroll
                        for (int mi = 0; mi < 2; ++mi) { MMA3(acc[g][nt][mi], ah[mi], al[mi], b); }
                    }
                }
            }
#pragma unroll 2
            for (int ch = 8; ch < 16; ++ch) {          // K 128..255 (h1): R,Z,N
                const int cb = ch * 1024 + fragbase;
                uint32_t ah[2][4], al[2][4];
#pragma unroll
                for (int mi = 0; mi < 2; ++mi) {
                    uint4 vh = *(const uint4*)(shi + cb + mi * 512);
                    uint4 vl = *(const uint4*)(slo + cb + mi * 512);
                    ah[mi][0] = vh.x; ah[mi][1] = vh.y; ah[mi][2] = vh.z; ah[mi][3] = vh.w;
                    al[mi][0] = vl.x; al[mi][1] = vl.y; al[mi][2] = vl.z; al[mi][3] = vl.w;
                }
                const int gl[3] = {0, 1, 3};
#pragma unroll
                for (int gi = 0; gi < 3; ++gi) {
                    const int g = gl[gi];
#pragma unroll
                    for (int nt = 0; nt < 2; ++nt) {
                        uint4 b = g_Q1[((ch * 4 + g) * 16 + js0 + nt) * 32 + lane];
#pragma unroll
                        for (int mi = 0; mi < 2; ++mi) { MMA3(acc[g][nt][mi], ah[mi], al[mi], b); }
                    }
                }
            }
            // epilogue L1 (pass p)
#pragma unroll
            for (int mi = 0; mi < 2; ++mi) {
                const int hpaddr = (8 + p * 4 + wn) * 1024 + fragbase + mi * 512;
                uint4 ph = *(const uint4*)(shi + hpaddr);
                uint4 pl = *(const uint4*)(slo + hpaddr);
                uint32_t phA[4] = {ph.x, ph.y, ph.z, ph.w};
                uint32_t plA[4] = {pl.x, pl.y, pl.z, pl.w};
                uint32_t vhi[4], vlo[4];
#pragma unroll
                for (int half = 0; half < 2; ++half) {
#pragma unroll
                    for (int nt = 0; nt < 2; ++nt) {
                        const int fi = nt * 2 + half;
                        const int jb = p * 64 + wn * 16 + nt * 8 + (lane & 3) * 2;
                        float hp[2] = { bf_lo(phA[fi]) + bf_lo(plA[fi]),
                                        bf_hi(phA[fi]) + bf_hi(plA[fi]) };
                        float h2[2];
#pragma unroll
                        for (int e = 0; e < 2; ++e) {
                            int j = jb + e;
                            int c = half * 2 + e;
                            float rr = sigf(acc[0][nt][mi][c] + sb[512 + j]);
                            float zz = sigf(acc[1][nt][mi][c] + sb[640 + j]);
                            float nn = tanhfast(acc[2][nt][mi][c] + sb[768 + j] +
                                                rr * (acc[3][nt][mi][c] + sb[896 + j]));
                            h2[e] = (1.f - zz) * nn + zz * hp[e];
                        }
                        vhi[fi] = pack_bf16x2(h2[0], h2[1], vlo[fi]);
                    }
                }
                hqh[p][mi] = make_uint4(vhi[0], vhi[1], vhi[2], vhi[3]);
                hql[p][mi] = make_uint4(vlo[0], vlo[1], vlo[2], vlo[3]);
            }
        }
        __syncthreads();
#pragma unroll
        for (int p = 0; p < 2; ++p)
#pragma unroll
            for (int mi = 0; mi < 2; ++mi) {
                const int a = (8 + p * 4 + wn) * 1024 + fragbase + mi * 512;
                *(uint4*)(shi + a) = hqh[p][mi];
                *(uint4*)(slo + a) = hql[p][mi];
            }
        // no barrier here (redundant): next-step L0 touches only chunks 0-7 +
        // sX; every reader of chunks 8-15 (L1 MMA of t+1, per-warp-own L1
        // epilogue hp) is separated from this STS by the two syncs above.
    }
    __syncthreads();

    // final: h1 smem -> g_h1 fp32 (32 rows x 64 col-pairs)
    for (int i = tid; i < 2048; i += 128) {
        int r = i >> 6, j = (i & 63) * 2;
        int chunk = 8 + ((i & 63) >> 3);
        int q = i & 7, pc = q & 3, nt = q >> 2;
        int gr = r & 7, half = (r >> 3) & 1, mi = r >> 4;
        int off = chunk * 1024 + mi * 512 + (gr * 4 + pc) * 16 + (nt * 2 + half) * 4;
        uint32_t phi = *(const uint32_t*)(shi + off);
        uint32_t plo = *(const uint32_t*)(slo + off);
        float2 o = make_float2(bf_lo(phi) + bf_lo(plo), bf_hi(phi) + bf_hi(plo));
        *(float2*)(g_h1 + (size_t)(m0 + r) * TH + j) = o;
    }
}

// ---- node stage 1: LN(h1) -> xp, attention scores ----
__global__ void node_stage1(const float* __restrict__ ln_g, const float* __restrict__ ln_b,
                            const float* __restrict__ gatW,
                            const float* __restrict__ att_s, const float* __restrict__ att_d) {
    __shared__ float ts[8][TH];
    const int lane = threadIdx.x & 31, warp = threadIdx.x >> 5;
    const int m = blockIdx.x * 8 + warp;
    const float* hr = g_h1 + (size_t)m * TH;
    float v[4], s = 0.f, sq = 0.f;
#pragma unroll
    for (int i = 0; i < 4; ++i) { v[i] = hr[lane + 32 * i]; s += v[i]; sq += v[i] * v[i]; }
#pragma unroll
    for (int o = 16; o; o >>= 1) {
        s  += __shfl_xor_sync(0xffffffffu, s, o);
        sq += __shfl_xor_sync(0xffffffffu, sq, o);
    }
    float mu = s * (1.f / TH), var = sq * (1.f / TH) - mu * mu, inv = rsqrtf(var + 1e-5f);
#pragma unroll
    for (int i = 0; i < 4; ++i) {
        int k = lane + 32 * i;
        ts[warp][k] = (v[i] - mu) * inv * ln_g[k] + ln_b[k];
    }
    __syncwarp();
    float x0 = 0.f, x1 = 0.f;
#pragma unroll 4
    for (int k = 0; k < TH; ++k) {
        float tv = ts[warp][k];
        x0 = fmaf(tv, gatW[k * SH + lane], x0);
        x1 = fmaf(tv, gatW[k * SH + lane + 32], x1);
    }
    g_xp[(size_t)m * SH + lane] = x0;
    g_xp[(size_t)m * SH + lane + 32] = x1;
    float ps0 = x0 * att_s[lane], ps1 = x1 * att_s[lane + 32];
    float pd0 = x0 * att_d[lane], pd1 = x1 * att_d[lane + 32];
#pragma unroll
    for (int o = 8; o; o >>= 1) {
        ps0 += __shfl_xor_sync(0xffffffffu, ps0, o, 16);
        ps1 += __shfl_xor_sync(0xffffffffu, ps1, o, 16);
        pd0 += __shfl_xor_sync(0xffffffffu, pd0, o, 16);
        pd1 += __shfl_xor_sync(0xffffffffu, pd1, o, 16);
    }
    if ((lane & 15) == 0) {
        int h = lane >> 4;
        g_asrc[m * HEADS + h] = ps0;  g_asrc[m * HEADS + 2 + h] = ps1;
        g_adst[m * HEADS + h] = pd0;  g_adst[m * HEADS + 2 + h] = pd1;
    }
}

// ---- edge pass: vectorized red.global.add.v4.f32 ----
__global__ void edge_kernel(const int* __restrict__ ei32) {
    int idx = blockIdx.x * blockDim.x + threadIdx.x;
    if (idx >= ET * HEADS) return;
    int h = idx & 3, e = idx >> 2, s, d;
    if (e < Bv * EB) {
        int g = e / EB, i = e - g * EB;
        if (g_ei_is64) { s = ei32[2 * i] + g * Nv; d = ei32[2 * (EB + i)] + g * Nv; }
        else           { s = ei32[i] + g * Nv;     d = ei32[EB + i] + g * Nv; }
    } else s = d = e - Bv * EB;
    float al = g_asrc[s * HEADS + h] + g_adst[d * HEADS + h];
    al = al > 0.f ? al : 0.2f * al;
    float ex = __expf(al);
    atomicAdd(&g_den[d * HEADS + h], ex);
    const float* xr = g_xp + (size_t)s * SH + h * 16;
    float* ar = g_agg + (size_t)d * SH + h * 16;
#pragma unroll
    for (int c4 = 0; c4 < 4; ++c4) {
        float4 xv = *(const float4*)(xr + c4 * 4);
        red_add_v4(ar + c4 * 4, ex * xv.x, ex * xv.y, ex * xv.z, ex * xv.w);
    }
}

// ---- node stage 2 ----
__global__ void node_stage2(const float* __restrict__ gat_b,
                            const float* __restrict__ ln_g, const float* __restrict__ ln_b,
                            const float* __restrict__ W1, const float* __restrict__ b1,
                            const float* __restrict__ W2, const float* __restrict__ b2,
                            float* __restrict__ out) {
    __shared__ float ys[8][SH];
    const int lane = threadIdx.x & 31, warp = threadIdx.x >> 5;
    const int m = blockIdx.x * 8 + warp;
    float s0 = g_agg[(size_t)m * SH + lane]      / g_den[m * HEADS + (lane >> 4)]     + gat_b[lane];
    float s1 = g_agg[(size_t)m * SH + lane + 32] / g_den[m * HEADS + 2 + (lane >> 4)] + gat_b[lane + 32];
    float s = s0 + s1, sq = s0 * s0 + s1 * s1;
#pragma unroll
    for (int o = 16; o; o >>= 1) {
        s  += __shfl_xor_sync(0xffffffffu, s, o);
        sq += __shfl_xor_sync(0xffffffffu, sq, o);
    }
    float mu = s * (1.f / SH), var = sq * (1.f / SH) - mu * mu, inv = rsqrtf(var + 1e-5f);
    float y0 = (s0 - mu) * inv * ln_g[lane] + ln_b[lane];
    float y1 = (s1 - mu) * inv * ln_g[lane + 32] + ln_b[lane + 32];
    y0 = y0 > 0.f ? y0 : 0.2f * y0;
    y1 = y1 > 0.f ? y1 : 0.2f * y1;
    ys[warp][lane] = y0; ys[warp][lane + 32] = y1;
    __syncwarp();
    float acc = b1[lane];
#pragma unroll
    for (int k = 0; k < SH; ++k) acc = fmaf(ys[warp][k], W1[k * 32 + lane], acc);
    acc = acc > 0.f ? acc : 0.2f * acc;
    float p = acc * W2[lane];
#pragma unroll
    for (int o = 16; o; o >>= 1) p += __shfl_xor_sync(0xffffffffu, p, o);
    if (lane == 0) out[m] = p + b2[0];
}

extern "C" void kernel_launch(void* const* d_in, const int* in_sizes, int n_in,
                              void* d_out, int out_size) {
    const float* x     = (const float*)d_in[0];
    const int*   ei32  = (const int*)d_in[1];
    const float* W_ih0 = (const float*)d_in[2];
    const float* W_hh0 = (const float*)d_in[3];
    const float* b_ih0 = (const float*)d_in[4];
    const float* b_hh0 = (const float*)d_in[5];
    const float* W_ih1 = (const float*)d_in[6];
    const float* W_hh1 = (const float*)d_in[7];
    const float* b_ih1 = (const float*)d_in[8];
    const float* b_hh1 = (const float*)d_in[9];
    const float* ln1_g = (const float*)d_in[10];
    const float* ln1_b = (const float*)d_in[11];
    const float* gat_W = (const float*)d_in[12];
    const float* att_s = (const float*)d_in[13];
    const float* att_d = (const float*)d_in[14];
    const float* gat_b = (const float*)d_in[15];
    const float* ln2_g = (const float*)d_in[16];
    const float* ln2_b = (const float*)d_in[17];
    const float* regW1 = (const float*)d_in[18];
    const float* regb1 = (const float*)d_in[19];
    const float* regW2 = (const float*)d_in[20];
    const float* regb2 = (const float*)d_in[21];
    float* out = (float*)d_out;

    cudaFuncSetAttribute(gru_all, cudaFuncAttributeMaxDynamicSharedMemorySize, SM_TOT);

    detect_ei_kernel<<<1, 256>>>(ei32);
    prep_pack<<<(Q1N + Q0N + 255) / 256, 256>>>(W_ih1, W_hh1, W_hh0);
    zero_kernel<<<2048, 512>>>();

    gru_all<<<Mn / 32, 128, SM_TOT>>>(x, W_ih0, b_ih0, b_hh0, b_ih1, b_hh1);

    node_stage1<<<Mn / 8, 256>>>(ln1_g, ln1_b, gat_W, att_s, att_d);
    edge_kernel<<<(ET * HEADS + 255) / 256, 256>>>(ei32);
    node_stage2<<<Mn / 8, 256>>>(gat_b, ln2_g, ln2_b, regW1, regb1, regW2, regb2, out);
}